// round 5
// baseline (speedup 1.0000x reference)
#include <cuda_runtime.h>
#include <math.h>

typedef unsigned long long ull;

#define NCTA 128
#define THREADS 1024
#define WS_ROW 1036
#define WS_FLOATS (24 * WS_ROW)
#define HB_ROW 34
#define HBUF_FLOATS (64 * HB_ROW)
#define HB_FLOATS (8 * HBUF_FLOATS)
#define SCAN_SMEM ((WS_FLOATS + HB_FLOATS) * 4)

// ---------------- device scratch (allocation-free contract) -----------------
__device__ float g_EW[128 * 3 * 1024];    // EW[v][g][j] includes input bias
__device__ float g_Wc[1024 * 128];        // Wh @ Wo
__device__ float g_bc[128];               // bh @ Wo + bo
__device__ float g_h[2 * 64 * 1024];      // ping-pong hidden state
__device__ float g_y[64u * 512u * 1024u]; // all hidden states [b][t][j]
__device__ unsigned g_cnt;                // monotonic barrier counter
__device__ unsigned g_gen;                // barrier generation

// ---------------- f32x2 helpers ---------------------------------------------
__device__ __forceinline__ ull fma2(ull a, ull b, ull c) {
    ull d;
    asm("fma.rn.f32x2 %0, %1, %2, %3;" : "=l"(d) : "l"(a), "l"(b), "l"(c));
    return d;
}
__device__ __forceinline__ float2 unpk2(ull v) {
    unsigned lo, hi;
    asm("mov.b64 {%0, %1}, %2;" : "=r"(lo), "=r"(hi) : "l"(v));
    return make_float2(__uint_as_float(lo), __uint_as_float(hi));
}

// ---------------- prep: EW table --------------------------------------------
__global__ __launch_bounds__(256) void prep_ew(
    const float* __restrict__ emb,
    const float* __restrict__ Wir, const float* __restrict__ bir,
    const float* __restrict__ Wiz, const float* __restrict__ biz,
    const float* __restrict__ Win, const float* __restrict__ bin_)
{
    __shared__ float se[128];
    int v = blockIdx.x, tid = threadIdx.x;
    if (tid < 128) se[tid] = emb[v * 128 + tid];
    __syncthreads();
    for (int i = tid; i < 3072; i += 256) {
        int g = i >> 10, j = i & 1023;
        const float* W  = (g == 0) ? Wir : (g == 1) ? Wiz : Win;
        const float* bb = (g == 0) ? bir : (g == 1) ? biz : bin_;
        float acc = bb[j];
        #pragma unroll 8
        for (int e = 0; e < 128; ++e) acc += se[e] * W[e * 1024 + j];
        g_EW[v * 3072 + i] = acc;
    }
}

// ---------------- prep: carry copy + bc + barrier reset ---------------------
__global__ __launch_bounds__(256) void prep_misc(
    const float* __restrict__ carry, const float* __restrict__ bh,
    const float* __restrict__ Wo,    const float* __restrict__ bo)
{
    int bx = blockIdx.x, tid = threadIdx.x;
    if (bx < 64) {
        ((float4*)g_h)[bx * 256 + tid] = ((const float4*)carry)[bx * 256 + tid];
    } else {
        if (tid < 128) {
            float acc = bo[tid];
            for (int m = 0; m < 1024; ++m) acc += bh[m] * Wo[m * 128 + tid];
            g_bc[tid] = acc;
        }
        if (tid == 0) { g_cnt = 0u; g_gen = 0u; }
    }
}

// ---------------- tiled GEMM: C[M x 128] = A[M x 1024] @ B[1024 x 128] + bias
__global__ __launch_bounds__(256) void gemm128(
    const float* __restrict__ A, const float* __restrict__ Bm,
    const float* __restrict__ bias, float* __restrict__ C)
{
    __shared__ float As[32][132];
    __shared__ float Bs[32][128];
    int tid = threadIdx.x;
    int tx = tid & 15, ty = tid >> 4;
    int m0 = blockIdx.x * 128;

    float acc[8][8];
    #pragma unroll
    for (int i = 0; i < 8; ++i)
        #pragma unroll
        for (int j = 0; j < 8; ++j)
            acc[i][j] = bias ? bias[tx * 8 + j] : 0.0f;

    for (int k0 = 0; k0 < 1024; k0 += 32) {
        __syncthreads();
        #pragma unroll
        for (int i = 0; i < 4; ++i) {
            int idx = tid + i * 256;
            int m = idx >> 3, q = idx & 7;
            float4 v = *(const float4*)(A + (size_t)(m0 + m) * 1024 + k0 + q * 4);
            As[q * 4 + 0][m] = v.x; As[q * 4 + 1][m] = v.y;
            As[q * 4 + 2][m] = v.z; As[q * 4 + 3][m] = v.w;
        }
        #pragma unroll
        for (int i = 0; i < 4; ++i) {
            int idx = tid + i * 256;
            int r = idx >> 5, q = idx & 31;
            *(float4*)(&Bs[r][q * 4]) = *(const float4*)(Bm + (size_t)(k0 + r) * 128 + q * 4);
        }
        __syncthreads();
        #pragma unroll 4
        for (int kk = 0; kk < 32; ++kk) {
            float4 a0 = *(const float4*)(&As[kk][ty * 8]);
            float4 a1 = *(const float4*)(&As[kk][ty * 8 + 4]);
            float4 b0 = *(const float4*)(&Bs[kk][tx * 8]);
            float4 b1 = *(const float4*)(&Bs[kk][tx * 8 + 4]);
            float av[8] = {a0.x, a0.y, a0.z, a0.w, a1.x, a1.y, a1.z, a1.w};
            float bv[8] = {b0.x, b0.y, b0.z, b0.w, b1.x, b1.y, b1.z, b1.w};
            #pragma unroll
            for (int i = 0; i < 8; ++i)
                #pragma unroll
                for (int j = 0; j < 8; ++j)
                    acc[i][j] = fmaf(av[i], bv[j], acc[i][j]);
        }
    }
    #pragma unroll
    for (int i = 0; i < 8; ++i) {
        float* cp = C + (size_t)(m0 + ty * 8 + i) * 128 + tx * 8;
        *(float4*)cp       = make_float4(acc[i][0], acc[i][1], acc[i][2], acc[i][3]);
        *(float4*)(cp + 4) = make_float4(acc[i][4], acc[i][5], acc[i][6], acc[i][7]);
    }
}

// ---------------- persistent GRU scan (1024 thr, 8-way k-split, k-packed) ---
__global__ void __launch_bounds__(1024, 1) scan_kernel(
    const int*   __restrict__ toks,
    const float* __restrict__ Whr, const float* __restrict__ Whz,
    const float* __restrict__ Whn, const float* __restrict__ bhn)
{
    extern __shared__ float sm[];
    float* ws = sm;                    // [24][1036]  row = jj8*3+g, k-major
    float* hb = sm + WS_FLOATS;        // [8][64][34]

    const int tid = threadIdx.x, bx = blockIdx.x;
    const int kh = tid >> 7;           // k-eighth 0..7
    const int r  = tid & 127;
    const int b2 = r >> 2, jp = r & 3;
    const int be = b2 * 2, bo = be + 1;
    const int jbase = bx * 8;
    const int j0 = jbase + jp * 2;

    // ---- load recurrent weights into smem once: ws[jj8*3+g][k] = Wg[k][jbase+jj8]
    for (int i = tid; i < 24 * 1024; i += THREADS) {
        int k = i & 1023, row = i >> 10;
        int jj8 = row / 3, g = row - jj8 * 3;
        const float* Wg = (g == 0) ? Whr : (g == 1) ? Whz : Whn;
        ws[row * WS_ROW + k] = Wg[(size_t)k * 1024 + jbase + jj8];
    }
    const float* w_r0 = ws + ((jp * 2 + 0) * 3 + 0) * WS_ROW;
    const float* w_z0 = ws + ((jp * 2 + 0) * 3 + 1) * WS_ROW;
    const float* w_n0 = ws + ((jp * 2 + 0) * 3 + 2) * WS_ROW;
    const float* w_r1 = ws + ((jp * 2 + 1) * 3 + 0) * WS_ROW;
    const float* w_z1 = ws + ((jp * 2 + 1) * 3 + 1) * WS_ROW;
    const float* w_n1 = ws + ((jp * 2 + 1) * 3 + 2) * WS_ROW;
    const float* he_ptr = hb + kh * HBUF_FLOATS + be * HB_ROW;
    const float* ho_ptr = hb + kh * HBUF_FLOATS + bo * HB_ROW;
    const float2 bhn2 = *(const float2*)(bhn + j0);
    __syncthreads();

    for (int t = 0; t < 512; ++t) {
        const int p = t & 1;
        const float* hsrc = g_h + p * 65536;
        float*       hdst = g_h + (p ^ 1) * 65536;

        int tok_e = 0, tok_o = 0;
        if (kh == 0) {
            tok_e = toks[(be << 9) + t];
            tok_o = toks[(bo << 9) + t];
        }

        ull a_r0e = 0, a_z0e = 0, a_n0e = 0, a_r1e = 0, a_z1e = 0, a_n1e = 0;
        ull a_r0o = 0, a_z0o = 0, a_n0o = 0, a_r1o = 0, a_z1o = 0, a_n1o = 0;

        #pragma unroll 1
        for (int ph = 0; ph < 4; ++ph) {
            __syncthreads();                 // buffers free (prior compute done)
            #pragma unroll
            for (int c4 = 0; c4 < 4; ++c4) { // stage 32-k chunk of all 8 buffers
                int id = tid + (c4 << 10);
                int q = id >> 9, rem = id & 511, b = rem >> 3, c = rem & 7;
                const float* src = hsrc + b * 1024 + q * 128 + ph * 32 + c * 4;
                float* dst = hb + q * HBUF_FLOATS + b * HB_ROW + c * 4;
                unsigned sdst = (unsigned)__cvta_generic_to_shared(dst);
                // 8-byte copies: HB_ROW=34 rows are 8B-aligned, not 16B
                asm volatile("cp.async.ca.shared.global [%0], [%1], 8;"
                             :: "r"(sdst), "l"(src));
                asm volatile("cp.async.ca.shared.global [%0], [%1], 8;"
                             :: "r"(sdst + 8u), "l"(src + 2));
            }
            asm volatile("cp.async.commit_group;" ::: "memory");
            asm volatile("cp.async.wait_group 0;" ::: "memory");
            __syncthreads();

            const int kg = (kh << 7) + (ph << 5);
            #pragma unroll
            for (int kk = 0; kk < 32; kk += 4) {
                // h reads as LDS.64 (8B-aligned rows)
                ull he0 = *(const ull*)(he_ptr + kk);
                ull he1 = *(const ull*)(he_ptr + kk + 2);
                ull ho0 = *(const ull*)(ho_ptr + kk);
                ull ho1 = *(const ull*)(ho_ptr + kk + 2);
                ulonglong2 vr0 = *(const ulonglong2*)(w_r0 + kg + kk);
                ulonglong2 vz0 = *(const ulonglong2*)(w_z0 + kg + kk);
                ulonglong2 vn0 = *(const ulonglong2*)(w_n0 + kg + kk);
                ulonglong2 vr1 = *(const ulonglong2*)(w_r1 + kg + kk);
                ulonglong2 vz1 = *(const ulonglong2*)(w_z1 + kg + kk);
                ulonglong2 vn1 = *(const ulonglong2*)(w_n1 + kg + kk);
                a_r0e = fma2(he0, vr0.x, a_r0e); a_r0e = fma2(he1, vr0.y, a_r0e);
                a_z0e = fma2(he0, vz0.x, a_z0e); a_z0e = fma2(he1, vz0.y, a_z0e);
                a_n0e = fma2(he0, vn0.x, a_n0e); a_n0e = fma2(he1, vn0.y, a_n0e);
                a_r1e = fma2(he0, vr1.x, a_r1e); a_r1e = fma2(he1, vr1.y, a_r1e);
                a_z1e = fma2(he0, vz1.x, a_z1e); a_z1e = fma2(he1, vz1.y, a_z1e);
                a_n1e = fma2(he0, vn1.x, a_n1e); a_n1e = fma2(he1, vn1.y, a_n1e);
                a_r0o = fma2(ho0, vr0.x, a_r0o); a_r0o = fma2(ho1, vr0.y, a_r0o);
                a_z0o = fma2(ho0, vz0.x, a_z0o); a_z0o = fma2(ho1, vz0.y, a_z0o);
                a_n0o = fma2(ho0, vn0.x, a_n0o); a_n0o = fma2(ho1, vn0.y, a_n0o);
                a_r1o = fma2(ho0, vr1.x, a_r1o); a_r1o = fma2(ho1, vr1.y, a_r1o);
                a_z1o = fma2(ho0, vz1.x, a_z1o); a_z1o = fma2(ho1, vz1.y, a_z1o);
                a_n1o = fma2(ho0, vn1.x, a_n1o); a_n1o = fma2(ho1, vn1.y, a_n1o);
            }
        }

        // ---- horizontal sums (even-k + odd-k partials) ----
        float2 u;
        u = unpk2(a_r0e); float sr0e = u.x + u.y;
        u = unpk2(a_r1e); float sr1e = u.x + u.y;
        u = unpk2(a_z0e); float sz0e = u.x + u.y;
        u = unpk2(a_z1e); float sz1e = u.x + u.y;
        u = unpk2(a_n0e); float sn0e = u.x + u.y;
        u = unpk2(a_n1e); float sn1e = u.x + u.y;
        u = unpk2(a_r0o); float sr0o = u.x + u.y;
        u = unpk2(a_r1o); float sr1o = u.x + u.y;
        u = unpk2(a_z0o); float sz0o = u.x + u.y;
        u = unpk2(a_z1o); float sz1o = u.x + u.y;
        u = unpk2(a_n0o); float sn0o = u.x + u.y;
        u = unpk2(a_n1o); float sn1o = u.x + u.y;

        __syncthreads();                 // all compute reads of hb done
        float* red = hb;                 // reuse h buffers for reduction
        {
            float4* mp = (float4*)(red + tid * 12);
            mp[0] = make_float4(sr0e, sr1e, sz0e, sz1e);
            mp[1] = make_float4(sn0e, sn1e, sr0o, sr1o);
            mp[2] = make_float4(sz0o, sz1o, sn0o, sn1o);
        }
        __syncthreads();

        if (kh == 0) {
            #pragma unroll
            for (int q = 1; q < 8; ++q) {
                const float4* pp = (const float4*)(red + (tid + (q << 7)) * 12);
                float4 x0 = pp[0], x1 = pp[1], x2 = pp[2];
                sr0e += x0.x; sr1e += x0.y; sz0e += x0.z; sz1e += x0.w;
                sn0e += x1.x; sn1e += x1.y; sr0o += x1.z; sr1o += x1.w;
                sz0o += x2.x; sz1o += x2.y; sn0o += x2.z; sn1o += x2.w;
            }
            const float* ewp_e = g_EW + tok_e * 3072;
            const float* ewp_o = g_EW + tok_o * 3072;
            float2 ewr_e = *(const float2*)(ewp_e + j0);
            float2 ewz_e = *(const float2*)(ewp_e + 1024 + j0);
            float2 ewn_e = *(const float2*)(ewp_e + 2048 + j0);
            float2 ewr_o = *(const float2*)(ewp_o + j0);
            float2 ewz_o = *(const float2*)(ewp_o + 1024 + j0);
            float2 ewn_o = *(const float2*)(ewp_o + 2048 + j0);
            float2 hold_e = *(const float2*)(hsrc + be * 1024 + j0);
            float2 hold_o = *(const float2*)(hsrc + bo * 1024 + j0);

            float r0 = 1.0f / (1.0f + expf(-(ewr_e.x + sr0e)));
            float r1 = 1.0f / (1.0f + expf(-(ewr_e.y + sr1e)));
            float z0 = 1.0f / (1.0f + expf(-(ewz_e.x + sz0e)));
            float z1 = 1.0f / (1.0f + expf(-(ewz_e.y + sz1e)));
            float n0 = tanhf(ewn_e.x + r0 * (sn0e + bhn2.x));
            float n1 = tanhf(ewn_e.y + r1 * (sn1e + bhn2.y));
            float2 hv_e = make_float2((1.0f - z0) * n0 + z0 * hold_e.x,
                                      (1.0f - z1) * n1 + z1 * hold_e.y);

            float q0 = 1.0f / (1.0f + expf(-(ewr_o.x + sr0o)));
            float q1 = 1.0f / (1.0f + expf(-(ewr_o.y + sr1o)));
            float y0 = 1.0f / (1.0f + expf(-(ewz_o.x + sz0o)));
            float y1 = 1.0f / (1.0f + expf(-(ewz_o.y + sz1o)));
            float m0 = tanhf(ewn_o.x + q0 * (sn0o + bhn2.x));
            float m1 = tanhf(ewn_o.y + q1 * (sn1o + bhn2.y));
            float2 hv_o = make_float2((1.0f - y0) * m0 + y0 * hold_o.x,
                                      (1.0f - y1) * m1 + y1 * hold_o.y);

            *(float2*)(hdst + be * 1024 + j0) = hv_e;
            *(float2*)(hdst + bo * 1024 + j0) = hv_o;
            *(float2*)(g_y + (size_t)((be << 9) + t) * 1024 + j0) = hv_e;
            *(float2*)(g_y + (size_t)((bo << 9) + t) * 1024 + j0) = hv_o;
        }

        // ---- grid barrier (fence-light, monotonic) ----
        __syncthreads();
        if (tid == 0) {
            unsigned target = (unsigned)(t + 1) * (unsigned)NCTA;
            unsigned old;
            asm volatile("atom.acq_rel.gpu.add.u32 %0, [%1], 1;"
                         : "=r"(old) : "l"(&g_cnt) : "memory");
            if (old == target - 1u) {
                asm volatile("st.release.gpu.u32 [%0], %1;"
                             :: "l"(&g_gen), "r"((unsigned)(t + 1)) : "memory");
            } else {
                unsigned v;
                do {
                    asm volatile("ld.acquire.gpu.u32 %0, [%1];"
                                 : "=r"(v) : "l"(&g_gen) : "memory");
                } while (v < (unsigned)(t + 1));
            }
        }
        __syncthreads();
    }
}

// ---------------- carry_out copy --------------------------------------------
__global__ __launch_bounds__(256) void copy_carry(float* __restrict__ out)
{
    ((float4*)out)[blockIdx.x * 256 + threadIdx.x] =
        ((const float4*)g_h)[blockIdx.x * 256 + threadIdx.x];
}

// ---------------- launch ----------------------------------------------------
extern "C" void kernel_launch(void* const* d_in, const int* in_sizes, int n_in,
                              void* d_out, int out_size)
{
    const int*   toks  = (const int*)  d_in[0];
    const float* carry = (const float*)d_in[1];
    const float* emb   = (const float*)d_in[2];
    const float* Wir   = (const float*)d_in[3];
    const float* bir   = (const float*)d_in[4];
    const float* Whr   = (const float*)d_in[5];
    const float* Wiz   = (const float*)d_in[6];
    const float* biz   = (const float*)d_in[7];
    const float* Whz   = (const float*)d_in[8];
    const float* Win   = (const float*)d_in[9];
    const float* bin_  = (const float*)d_in[10];
    const float* Whn   = (const float*)d_in[11];
    const float* bhn   = (const float*)d_in[12];
    const float* Wh    = (const float*)d_in[13];
    const float* bh    = (const float*)d_in[14];
    const float* Wo    = (const float*)d_in[15];
    const float* bo    = (const float*)d_in[16];
    float* out = (float*)d_out;

    void *pY = 0, *pWc = 0, *pbc = 0;
    cudaGetSymbolAddress(&pY,  g_y);
    cudaGetSymbolAddress(&pWc, g_Wc);
    cudaGetSymbolAddress(&pbc, g_bc);

    cudaFuncSetAttribute(scan_kernel, cudaFuncAttributeMaxDynamicSharedMemorySize, SCAN_SMEM);

    prep_ew<<<128, 256>>>(emb, Wir, bir, Wiz, biz, Win, bin_);
    gemm128<<<8, 256>>>(Wh, Wo, (const float*)0, (float*)pWc);   // Wc = Wh @ Wo
    prep_misc<<<65, 256>>>(carry, bh, Wo, bo);
    scan_kernel<<<NCTA, THREADS, SCAN_SMEM>>>(toks, Whr, Whz, Whn, bhn);
    copy_carry<<<64, 256>>>(out);
    gemm128<<<256, 256>>>((const float*)pY, (const float*)pWc, (const float*)pbc,
                          out + 65536);                           // logits
}

// round 7
// speedup vs baseline: 1.1842x; 1.1842x over previous
#include <cuda_runtime.h>
#include <math.h>

typedef unsigned long long ull;

#define NCTA 128
#define THREADS 512
#define WSU 514                                   // ull per weight row (pad: conflict-free jp banks)
#define WS_ULL (24 * WSU)                         // 98688 B
#define HP_ULL (64 * 64)                          // one 32KB sub-buffer: 64 kpair-rows x 64 batches
#define SCAN_SMEM ((WS_ULL + 2 * HP_ULL) * 8)     // 164224 B

// ---------------- device scratch (allocation-free contract) -----------------
__device__ float g_EW[128 * 3 * 1024];            // EW[v][g][j] includes input bias
__device__ float g_Wc[1024 * 128];                // Wh @ Wo
__device__ float g_bc[128];                       // bh @ Wo + bo
__device__ __align__(16) ull g_h2[2 * 512 * 64];  // ping-pong h, packed [kpair][batch]
__device__ float g_y[64u * 512u * 1024u];         // all hidden states [b][t][j]
__device__ unsigned g_cnt;                        // monotonic barrier counter
__device__ unsigned g_gen;                        // barrier generation

// ---------------- f32x2 helpers ---------------------------------------------
__device__ __forceinline__ ull fma2(ull a, ull b, ull c) {
    ull d;
    asm("fma.rn.f32x2 %0, %1, %2, %3;" : "=l"(d) : "l"(a), "l"(b), "l"(c));
    return d;
}
__device__ __forceinline__ ull pack2(float lo, float hi) {
    ull r;
    asm("mov.b64 %0, {%1, %2};" : "=l"(r) : "r"(__float_as_uint(lo)), "r"(__float_as_uint(hi)));
    return r;
}
__device__ __forceinline__ float2 unpk2(ull v) {
    unsigned lo, hi;
    asm("mov.b64 {%0, %1}, %2;" : "=r"(lo), "=r"(hi) : "l"(v));
    return make_float2(__uint_as_float(lo), __uint_as_float(hi));
}

// ---------------- prep: EW table --------------------------------------------
__global__ __launch_bounds__(256) void prep_ew(
    const float* __restrict__ emb,
    const float* __restrict__ Wir, const float* __restrict__ bir,
    const float* __restrict__ Wiz, const float* __restrict__ biz,
    const float* __restrict__ Win, const float* __restrict__ bin_)
{
    __shared__ float se[128];
    int v = blockIdx.x, tid = threadIdx.x;
    if (tid < 128) se[tid] = emb[v * 128 + tid];
    __syncthreads();
    for (int i = tid; i < 3072; i += 256) {
        int g = i >> 10, j = i & 1023;
        const float* W  = (g == 0) ? Wir : (g == 1) ? Wiz : Win;
        const float* bb = (g == 0) ? bir : (g == 1) ? biz : bin_;
        float acc = bb[j];
        #pragma unroll 8
        for (int e = 0; e < 128; ++e) acc += se[e] * W[e * 1024 + j];
        g_EW[v * 3072 + i] = acc;
    }
}

// ---------------- prep: carry pack + bc + barrier reset ---------------------
__global__ __launch_bounds__(256) void prep_misc(
    const float* __restrict__ carry, const float* __restrict__ bh,
    const float* __restrict__ Wo,    const float* __restrict__ bo)
{
    int bx = blockIdx.x, tid = threadIdx.x;
    if (bx < 128) {
        int idx = bx * 256 + tid;           // 32768 ull
        int kp = idx >> 6, b = idx & 63;
        g_h2[idx] = pack2(carry[b * 1024 + 2 * kp], carry[b * 1024 + 2 * kp + 1]);
    } else {
        if (tid < 128) {
            float acc = bo[tid];
            for (int m = 0; m < 1024; ++m) acc += bh[m] * Wo[m * 128 + tid];
            g_bc[tid] = acc;
        }
        if (tid == 0) { g_cnt = 0u; g_gen = 0u; }
    }
}

// ---------------- tiled GEMM: C[M x 128] = A[M x 1024] @ B[1024 x 128] + bias
__global__ __launch_bounds__(256) void gemm128(
    const float* __restrict__ A, const float* __restrict__ Bm,
    const float* __restrict__ bias, float* __restrict__ C)
{
    __shared__ float As[32][132];
    __shared__ float Bs[32][128];
    int tid = threadIdx.x;
    int tx = tid & 15, ty = tid >> 4;
    int m0 = blockIdx.x * 128;

    float acc[8][8];
    #pragma unroll
    for (int i = 0; i < 8; ++i)
        #pragma unroll
        for (int j = 0; j < 8; ++j)
            acc[i][j] = bias ? bias[tx * 8 + j] : 0.0f;

    for (int k0 = 0; k0 < 1024; k0 += 32) {
        __syncthreads();
        #pragma unroll
        for (int i = 0; i < 4; ++i) {
            int idx = tid + i * 256;
            int m = idx >> 3, q = idx & 7;
            float4 v = *(const float4*)(A + (size_t)(m0 + m) * 1024 + k0 + q * 4);
            As[q * 4 + 0][m] = v.x; As[q * 4 + 1][m] = v.y;
            As[q * 4 + 2][m] = v.z; As[q * 4 + 3][m] = v.w;
        }
        #pragma unroll
        for (int i = 0; i < 4; ++i) {
            int idx = tid + i * 256;
            int r = idx >> 5, q = idx & 31;
            *(float4*)(&Bs[r][q * 4]) = *(const float4*)(Bm + (size_t)(k0 + r) * 128 + q * 4);
        }
        __syncthreads();
        #pragma unroll 4
        for (int kk = 0; kk < 32; ++kk) {
            float4 a0 = *(const float4*)(&As[kk][ty * 8]);
            float4 a1 = *(const float4*)(&As[kk][ty * 8 + 4]);
            float4 b0 = *(const float4*)(&Bs[kk][tx * 8]);
            float4 b1 = *(const float4*)(&Bs[kk][tx * 8 + 4]);
            float av[8] = {a0.x, a0.y, a0.z, a0.w, a1.x, a1.y, a1.z, a1.w};
            float bv[8] = {b0.x, b0.y, b0.z, b0.w, b1.x, b1.y, b1.z, b1.w};
            #pragma unroll
            for (int i = 0; i < 8; ++i)
                #pragma unroll
                for (int j = 0; j < 8; ++j)
                    acc[i][j] = fmaf(av[i], bv[j], acc[i][j]);
        }
    }
    #pragma unroll
    for (int i = 0; i < 8; ++i) {
        float* cp = C + (size_t)(m0 + ty * 8 + i) * 128 + tx * 8;
        *(float4*)cp       = make_float4(acc[i][0], acc[i][1], acc[i][2], acc[i][3]);
        *(float4*)(cp + 4) = make_float4(acc[i][4], acc[i][5], acc[i][6], acc[i][7]);
    }
}

// ---------------- persistent GRU scan (512 thr, 4b x 6o register tile) ------
__global__ void __launch_bounds__(512, 1) scan_kernel(
    const int*   __restrict__ toks,
    const float* __restrict__ Whr, const float* __restrict__ Whz,
    const float* __restrict__ Whn, const float* __restrict__ bhn)
{
    extern __shared__ ull smu[];
    ull* ws  = smu;                    // [24][514]  row = jj*3+g, kpair-packed
    ull* hpA = smu + WS_ULL;           // [64][64]
    ull* hpB = hpA + HP_ULL;           // [64][64]

    const int tid = threadIdx.x, bx = blockIdx.x;
    const int kh = tid >> 6;           // k-eighth 0..7
    const int r  = tid & 63;
    const int b4 = r >> 2;             // batch quad 0..15
    const int jp = r & 3;              // j-pair 0..3
    const int bb = b4 * 4;             // first batch of quad
    const int jbase = bx * 8;
    const int j0 = jbase + jp * 2;

    // ---- pack recurrent weights into smem once: ws[jj*3+g][kp] = (Wg[2kp][j], Wg[2kp+1][j])
    for (int g = 0; g < 3; ++g) {
        const float* Wg = (g == 0) ? Whr : (g == 1) ? Whz : Whn;
        for (int k = tid; k < 1024; k += THREADS) {
            float4 v0 = *(const float4*)(Wg + (size_t)k * 1024 + jbase);
            float4 v1 = *(const float4*)(Wg + (size_t)k * 1024 + jbase + 4);
            float vj[8] = {v0.x, v0.y, v0.z, v0.w, v1.x, v1.y, v1.z, v1.w};
            int kp = k >> 1, par = k & 1;
            #pragma unroll
            for (int jj = 0; jj < 8; ++jj)
                ((float*)(ws + (jj * 3 + g) * WSU + kp))[par] = vj[jj];
        }
    }
    const ull* wA = ws + (2 * jp + 0) * 3 * WSU;   // rows g=0..2 for j0
    const ull* wB = ws + (2 * jp + 1) * 3 * WSU;   // rows g=0..2 for j0+1
    const float2 bhn2 = *(const float2*)(bhn + j0);
    __syncthreads();

    for (int t = 0; t < 512; ++t) {
        const int p = t & 1;
        const ull* hsrc = g_h2 + p * 32768;
        ull*       hdst = g_h2 + (p ^ 1) * 32768;

        int tk[4];
        if (kh == 0) {
            #pragma unroll
            for (int bi = 0; bi < 4; ++bi) tk[bi] = toks[(bb + bi) * 512 + t];
        }

        // ---- stage sub 0 (full 32KB: 2048 x 16B) ----
        #pragma unroll
        for (int c = 0; c < 4; ++c) {
            int u = tid + c * 512;                  // 0..2047
            int lr = u >> 5, col = u & 31;
            const ull* src = hsrc + (lr * 64 + col * 2);
            unsigned sdst = (unsigned)__cvta_generic_to_shared(hpA + lr * 64 + col * 2);
            asm volatile("cp.async.ca.shared.global [%0], [%1], 16;" :: "r"(sdst), "l"(src));
        }
        asm volatile("cp.async.commit_group;" ::: "memory");

        ull acc[4][6];
        #pragma unroll
        for (int bi = 0; bi < 4; ++bi)
            #pragma unroll
            for (int o = 0; o < 6; ++o) acc[bi][o] = 0;

        #pragma unroll 1
        for (int s = 0; s < 8; ++s) {
            asm volatile("cp.async.wait_group 0;" ::: "memory");
            __syncthreads();
            if (s < 7) {                            // stage sub s+1 into other buffer
                ull* nb = ((s + 1) & 1) ? hpB : hpA;
                #pragma unroll
                for (int c = 0; c < 4; ++c) {
                    int u = tid + c * 512;
                    int lr = u >> 5, col = u & 31;
                    const ull* src = hsrc + (((s + 1) * 64 + lr) * 64 + col * 2);
                    unsigned sdst = (unsigned)__cvta_generic_to_shared(nb + lr * 64 + col * 2);
                    asm volatile("cp.async.ca.shared.global [%0], [%1], 16;" :: "r"(sdst), "l"(src));
                }
                asm volatile("cp.async.commit_group;" ::: "memory");
            }
            const ull* hbuf = (s & 1) ? hpB : hpA;
            const int kl0 = kh * 8;                 // local kpair base for this kh
            const int kg0 = s * 64 + kl0;           // global kpair base (weights)
            #pragma unroll
            for (int i = 0; i < 8; i += 2) {
                const ull* h0p = hbuf + (kl0 + i) * 64 + bb;
                ulonglong2 h0a = *(const ulonglong2*)(h0p);
                ulonglong2 h0b = *(const ulonglong2*)(h0p + 2);
                ulonglong2 h1a = *(const ulonglong2*)(h0p + 64);
                ulonglong2 h1b = *(const ulonglong2*)(h0p + 66);
                ulonglong2 wv[6];
                wv[0] = *(const ulonglong2*)(wA + 0 * WSU + kg0 + i);
                wv[1] = *(const ulonglong2*)(wA + 1 * WSU + kg0 + i);
                wv[2] = *(const ulonglong2*)(wA + 2 * WSU + kg0 + i);
                wv[3] = *(const ulonglong2*)(wB + 0 * WSU + kg0 + i);
                wv[4] = *(const ulonglong2*)(wB + 1 * WSU + kg0 + i);
                wv[5] = *(const ulonglong2*)(wB + 2 * WSU + kg0 + i);
                ull hA[4] = {h0a.x, h0a.y, h0b.x, h0b.y};
                ull hB[4] = {h1a.x, h1a.y, h1b.x, h1b.y};
                #pragma unroll
                for (int bi = 0; bi < 4; ++bi)
                    #pragma unroll
                    for (int o = 0; o < 6; ++o) {
                        acc[bi][o] = fma2(hA[bi], wv[o].x, acc[bi][o]);
                        acc[bi][o] = fma2(hB[bi], wv[o].y, acc[bi][o]);
                    }
            }
        }

        // ---- horizontal sums: 24 floats per thread ----
        float s24[6][4];
        #pragma unroll
        for (int o = 0; o < 6; ++o)
            #pragma unroll
            for (int bi = 0; bi < 4; ++bi) {
                float2 u2 = unpk2(acc[bi][o]);
                s24[o][bi] = u2.x + u2.y;
            }

        __syncthreads();                  // all compute reads of hp done
        float4* red4 = (float4*)hpA;      // [6][512] float4 (48KB)
        #pragma unroll
        for (int o = 0; o < 6; ++o)
            red4[o * 512 + tid] = make_float4(s24[o][0], s24[o][1], s24[o][2], s24[o][3]);

        float2 ewr[4], ewz[4], ewn[4], hold[4];
        if (kh == 0) {                    // issue tail loads early (overlap with sync+LDS)
            #pragma unroll
            for (int bi = 0; bi < 4; ++bi) {
                const float* ewp = g_EW + tk[bi] * 3072;
                ewr[bi] = *(const float2*)(ewp + j0);
                ewz[bi] = *(const float2*)(ewp + 1024 + j0);
                ewn[bi] = *(const float2*)(ewp + 2048 + j0);
                hold[bi] = unpk2(hsrc[(j0 >> 1) * 64 + bb + bi]);
            }
        }
        __syncthreads();

        if (kh == 0) {
            float4 sum[6];
            #pragma unroll
            for (int o = 0; o < 6; ++o) {
                float4 sv = red4[o * 512 + tid];
                #pragma unroll
                for (int q = 1; q < 8; ++q) {
                    float4 v = red4[o * 512 + tid + (q << 6)];
                    sv.x += v.x; sv.y += v.y; sv.z += v.z; sv.w += v.w;
                }
                sum[o] = sv;
            }
            #pragma unroll
            for (int bi = 0; bi < 4; ++bi) {
                float sr0 = (&sum[0].x)[bi], sz0 = (&sum[1].x)[bi], sn0 = (&sum[2].x)[bi];
                float sr1 = (&sum[3].x)[bi], sz1 = (&sum[4].x)[bi], sn1 = (&sum[5].x)[bi];
                float r0 = 1.0f / (1.0f + expf(-(ewr[bi].x + sr0)));
                float r1 = 1.0f / (1.0f + expf(-(ewr[bi].y + sr1)));
                float z0 = 1.0f / (1.0f + expf(-(ewz[bi].x + sz0)));
                float z1 = 1.0f / (1.0f + expf(-(ewz[bi].y + sz1)));
                float n0 = tanhf(ewn[bi].x + r0 * (sn0 + bhn2.x));
                float n1 = tanhf(ewn[bi].y + r1 * (sn1 + bhn2.y));
                float h0 = (1.0f - z0) * n0 + z0 * hold[bi].x;
                float h1 = (1.0f - z1) * n1 + z1 * hold[bi].y;
                hdst[(j0 >> 1) * 64 + bb + bi] = pack2(h0, h1);
                *(float2*)(g_y + (size_t)((bb + bi) * 512 + t) * 1024 + j0) =
                    make_float2(h0, h1);
            }
            __threadfence();              // make h/y visible before release
        }

        // ---- grid barrier (fence-light, monotonic) ----
        __syncthreads();
        if (tid == 0) {
            unsigned target = (unsigned)(t + 1) * (unsigned)NCTA;
            unsigned old;
            asm volatile("atom.acq_rel.gpu.add.u32 %0, [%1], 1;"
                         : "=r"(old) : "l"(&g_cnt) : "memory");
            if (old == target - 1u) {
                asm volatile("st.release.gpu.u32 [%0], %1;"
                             :: "l"(&g_gen), "r"((unsigned)(t + 1)) : "memory");
            } else {
                unsigned v;
                do {
                    asm volatile("ld.acquire.gpu.u32 %0, [%1];"
                                 : "=r"(v) : "l"(&g_gen) : "memory");
                } while (v < (unsigned)(t + 1));
            }
        }
        __syncthreads();
    }
}

// ---------------- carry_out unpack ------------------------------------------
__global__ __launch_bounds__(256) void copy_carry(float* __restrict__ out)
{
    int idx = blockIdx.x * 256 + threadIdx.x;      // 32768 ull; final h in buffer 0
    int kp = idx >> 6, b = idx & 63;
    *(float2*)(out + b * 1024 + 2 * kp) = unpk2(g_h2[idx]);
}

// ---------------- launch ----------------------------------------------------
extern "C" void kernel_launch(void* const* d_in, const int* in_sizes, int n_in,
                              void* d_out, int out_size)
{
    const int*   toks  = (const int*)  d_in[0];
    const float* carry = (const float*)d_in[1];
    const float* emb   = (const float*)d_in[2];
    const float* Wir   = (const float*)d_in[3];
    const float* bir   = (const float*)d_in[4];
    const float* Whr   = (const float*)d_in[5];
    const float* Wiz   = (const float*)d_in[6];
    const float* biz   = (const float*)d_in[7];
    const float* Whz   = (const float*)d_in[8];
    const float* Win   = (const float*)d_in[9];
    const float* bin_  = (const float*)d_in[10];
    const float* Whn   = (const float*)d_in[11];
    const float* bhn   = (const float*)d_in[12];
    const float* Wh    = (const float*)d_in[13];
    const float* bh    = (const float*)d_in[14];
    const float* Wo    = (const float*)d_in[15];
    const float* bo    = (const float*)d_in[16];
    float* out = (float*)d_out;

    void *pY = 0, *pWc = 0, *pbc = 0;
    cudaGetSymbolAddress(&pY,  g_y);
    cudaGetSymbolAddress(&pWc, g_Wc);
    cudaGetSymbolAddress(&pbc, g_bc);

    cudaFuncSetAttribute(scan_kernel, cudaFuncAttributeMaxDynamicSharedMemorySize, SCAN_SMEM);

    prep_ew<<<128, 256>>>(emb, Wir, bir, Wiz, biz, Win, bin_);
    gemm128<<<8, 256>>>(Wh, Wo, (const float*)0, (float*)pWc);   // Wc = Wh @ Wo
    prep_misc<<<129, 256>>>(carry, bh, Wo, bo);
    scan_kernel<<<NCTA, THREADS, SCAN_SMEM>>>(toks, Whr, Whz, Whn, bhn);
    copy_carry<<<128, 256>>>(out);
    gemm128<<<256, 256>>>((const float*)pY, (const float*)pWc, (const float*)pbc,
                          out + 65536);                           // logits
}

// round 8
// speedup vs baseline: 1.1869x; 1.0023x over previous
#include <cuda_runtime.h>
#include <math.h>

typedef unsigned long long ull;

#define NCTA 128
#define THREADS 512
#define WSU 514                                   // ull per weight row (pad: conflict-free jp banks)
#define WS_ULL (24 * WSU)                         // 98688 B
#define HP_ULL (64 * 64)                          // one 32KB sub-buffer: 64 kpair-rows x 64 batches
#define SCAN_SMEM ((WS_ULL + 2 * HP_ULL) * 8)     // 164224 B

// ---------------- device scratch (allocation-free contract) -----------------
__device__ float g_EW[128 * 3 * 1024];            // EW[v][g][j] includes input bias
__device__ float g_Wc[1024 * 128];                // Wh @ Wo
__device__ float g_bc[128];                       // bh @ Wo + bo
__device__ __align__(16) ull g_h2[2 * 512 * 64];  // ping-pong h, packed [kpair][batch]
__device__ float g_y[64u * 512u * 1024u];         // all hidden states [b][t][j]
__device__ unsigned g_cnt;                        // monotonic barrier counter
__device__ unsigned g_gen;                        // barrier generation

// ---------------- f32x2 helpers ---------------------------------------------
__device__ __forceinline__ ull fma2(ull a, ull b, ull c) {
    ull d;
    asm("fma.rn.f32x2 %0, %1, %2, %3;" : "=l"(d) : "l"(a), "l"(b), "l"(c));
    return d;
}
__device__ __forceinline__ ull pack2(float lo, float hi) {
    ull r;
    asm("mov.b64 %0, {%1, %2};" : "=l"(r) : "r"(__float_as_uint(lo)), "r"(__float_as_uint(hi)));
    return r;
}
__device__ __forceinline__ float2 unpk2(ull v) {
    unsigned lo, hi;
    asm("mov.b64 {%0, %1}, %2;" : "=r"(lo), "=r"(hi) : "l"(v));
    return make_float2(__uint_as_float(lo), __uint_as_float(hi));
}

// ---------------- prep: EW table --------------------------------------------
__global__ __launch_bounds__(256) void prep_ew(
    const float* __restrict__ emb,
    const float* __restrict__ Wir, const float* __restrict__ bir,
    const float* __restrict__ Wiz, const float* __restrict__ biz,
    const float* __restrict__ Win, const float* __restrict__ bin_)
{
    __shared__ float se[128];
    int v = blockIdx.x, tid = threadIdx.x;
    if (tid < 128) se[tid] = emb[v * 128 + tid];
    __syncthreads();
    for (int i = tid; i < 3072; i += 256) {
        int g = i >> 10, j = i & 1023;
        const float* W  = (g == 0) ? Wir : (g == 1) ? Wiz : Win;
        const float* bb = (g == 0) ? bir : (g == 1) ? biz : bin_;
        float acc = bb[j];
        #pragma unroll 8
        for (int e = 0; e < 128; ++e) acc += se[e] * W[e * 1024 + j];
        g_EW[v * 3072 + i] = acc;
    }
}

// ---------------- prep: carry pack + bc + barrier reset ---------------------
__global__ __launch_bounds__(256) void prep_misc(
    const float* __restrict__ carry, const float* __restrict__ bh,
    const float* __restrict__ Wo,    const float* __restrict__ bo)
{
    int bx = blockIdx.x, tid = threadIdx.x;
    if (bx < 128) {
        int idx = bx * 256 + tid;           // 32768 ull
        int kp = idx >> 6, b = idx & 63;
        g_h2[idx] = pack2(carry[b * 1024 + 2 * kp], carry[b * 1024 + 2 * kp + 1]);
    } else {
        if (tid < 128) {
            float acc = bo[tid];
            for (int m = 0; m < 1024; ++m) acc += bh[m] * Wo[m * 128 + tid];
            g_bc[tid] = acc;
        }
        if (tid == 0) { g_cnt = 0u; g_gen = 0u; }
    }
}

// ---------------- tiled GEMM: C[M x 128] = A[M x 1024] @ B[1024 x 128] + bias
__global__ __launch_bounds__(256) void gemm128(
    const float* __restrict__ A, const float* __restrict__ Bm,
    const float* __restrict__ bias, float* __restrict__ C)
{
    __shared__ float As[32][132];
    __shared__ float Bs[32][128];
    int tid = threadIdx.x;
    int tx = tid & 15, ty = tid >> 4;
    int m0 = blockIdx.x * 128;

    float acc[8][8];
    #pragma unroll
    for (int i = 0; i < 8; ++i)
        #pragma unroll
        for (int j = 0; j < 8; ++j)
            acc[i][j] = bias ? bias[tx * 8 + j] : 0.0f;

    for (int k0 = 0; k0 < 1024; k0 += 32) {
        __syncthreads();
        #pragma unroll
        for (int i = 0; i < 4; ++i) {
            int idx = tid + i * 256;
            int m = idx >> 3, q = idx & 7;
            float4 v = *(const float4*)(A + (size_t)(m0 + m) * 1024 + k0 + q * 4);
            As[q * 4 + 0][m] = v.x; As[q * 4 + 1][m] = v.y;
            As[q * 4 + 2][m] = v.z; As[q * 4 + 3][m] = v.w;
        }
        #pragma unroll
        for (int i = 0; i < 4; ++i) {
            int idx = tid + i * 256;
            int r = idx >> 5, q = idx & 31;
            *(float4*)(&Bs[r][q * 4]) = *(const float4*)(Bm + (size_t)(k0 + r) * 128 + q * 4);
        }
        __syncthreads();
        #pragma unroll 4
        for (int kk = 0; kk < 32; ++kk) {
            float4 a0 = *(const float4*)(&As[kk][ty * 8]);
            float4 a1 = *(const float4*)(&As[kk][ty * 8 + 4]);
            float4 b0 = *(const float4*)(&Bs[kk][tx * 8]);
            float4 b1 = *(const float4*)(&Bs[kk][tx * 8 + 4]);
            float av[8] = {a0.x, a0.y, a0.z, a0.w, a1.x, a1.y, a1.z, a1.w};
            float bv[8] = {b0.x, b0.y, b0.z, b0.w, b1.x, b1.y, b1.z, b1.w};
            #pragma unroll
            for (int i = 0; i < 8; ++i)
                #pragma unroll
                for (int j = 0; j < 8; ++j)
                    acc[i][j] = fmaf(av[i], bv[j], acc[i][j]);
        }
    }
    #pragma unroll
    for (int i = 0; i < 8; ++i) {
        float* cp = C + (size_t)(m0 + ty * 8 + i) * 128 + tx * 8;
        *(float4*)cp       = make_float4(acc[i][0], acc[i][1], acc[i][2], acc[i][3]);
        *(float4*)(cp + 4) = make_float4(acc[i][4], acc[i][5], acc[i][6], acc[i][7]);
    }
}

// ---------------- persistent GRU scan (512 thr, 4b x 6o register tile) ------
__global__ void __launch_bounds__(512, 1) scan_kernel(
    const int*   __restrict__ toks,
    const float* __restrict__ Whr, const float* __restrict__ Whz,
    const float* __restrict__ Whn, const float* __restrict__ bhn)
{
    extern __shared__ ull smu[];
    ull* ws  = smu;                    // [24][514]  row = jj*3+g, kpair-packed
    ull* hpA = smu + WS_ULL;           // [64][64]
    ull* hpB = hpA + HP_ULL;           // [64][64]

    const int tid = threadIdx.x, bx = blockIdx.x;
    const int kh = tid >> 6;           // k-eighth 0..7
    const int r  = tid & 63;
    const int b4 = r >> 2;             // batch quad 0..15
    const int jp = r & 3;              // j-pair 0..3
    const int bb = b4 * 4;             // first batch of quad
    const int jbase = bx * 8;
    const int j0 = jbase + jp * 2;

    // ---- pack recurrent weights into smem once: ws[jj*3+g][kp] = (Wg[2kp][j], Wg[2kp+1][j])
    for (int g = 0; g < 3; ++g) {
        const float* Wg = (g == 0) ? Whr : (g == 1) ? Whz : Whn;
        for (int k = tid; k < 1024; k += THREADS) {
            float4 v0 = *(const float4*)(Wg + (size_t)k * 1024 + jbase);
            float4 v1 = *(const float4*)(Wg + (size_t)k * 1024 + jbase + 4);
            float vj[8] = {v0.x, v0.y, v0.z, v0.w, v1.x, v1.y, v1.z, v1.w};
            int kp = k >> 1, par = k & 1;
            #pragma unroll
            for (int jj = 0; jj < 8; ++jj)
                ((float*)(ws + (jj * 3 + g) * WSU + kp))[par] = vj[jj];
        }
    }
    const ull* wA = ws + (2 * jp + 0) * 3 * WSU;   // rows g=0..2 for j0
    const ull* wB = ws + (2 * jp + 1) * 3 * WSU;   // rows g=0..2 for j0+1
    const float2 bhn2 = *(const float2*)(bhn + j0);
    __syncthreads();

    for (int t = 0; t < 512; ++t) {
        const int p = t & 1;
        const ull* hsrc = g_h2 + p * 32768;
        ull*       hdst = g_h2 + (p ^ 1) * 32768;

        int tk[4];
        if (kh == 0) {
            #pragma unroll
            for (int bi = 0; bi < 4; ++bi) tk[bi] = toks[(bb + bi) * 512 + t];
        }

        // ---- stage sub 0 (full 32KB: 2048 x 16B) ----
        #pragma unroll
        for (int c = 0; c < 4; ++c) {
            int u = tid + c * 512;                  // 0..2047
            int lr = u >> 5, col = u & 31;
            const ull* src = hsrc + (lr * 64 + col * 2);
            unsigned sdst = (unsigned)__cvta_generic_to_shared(hpA + lr * 64 + col * 2);
            asm volatile("cp.async.ca.shared.global [%0], [%1], 16;" :: "r"(sdst), "l"(src));
        }
        asm volatile("cp.async.commit_group;" ::: "memory");

        ull acc[4][6];
        #pragma unroll
        for (int bi = 0; bi < 4; ++bi)
            #pragma unroll
            for (int o = 0; o < 6; ++o) acc[bi][o] = 0;

        #pragma unroll 1
        for (int s = 0; s < 8; ++s) {
            asm volatile("cp.async.wait_group 0;" ::: "memory");
            __syncthreads();
            if (s < 7) {                            // stage sub s+1 into other buffer
                ull* nb = ((s + 1) & 1) ? hpB : hpA;
                #pragma unroll
                for (int c = 0; c < 4; ++c) {
                    int u = tid + c * 512;
                    int lr = u >> 5, col = u & 31;
                    const ull* src = hsrc + (((s + 1) * 64 + lr) * 64 + col * 2);
                    unsigned sdst = (unsigned)__cvta_generic_to_shared(nb + lr * 64 + col * 2);
                    asm volatile("cp.async.ca.shared.global [%0], [%1], 16;" :: "r"(sdst), "l"(src));
                }
                asm volatile("cp.async.commit_group;" ::: "memory");
            }
            const ull* hbuf = (s & 1) ? hpB : hpA;
            const int kl0 = kh * 8;                 // local kpair base for this kh
            const int kg0 = s * 64 + kl0;           // global kpair base (weights)
            #pragma unroll
            for (int i = 0; i < 8; i += 2) {
                const ull* h0p = hbuf + (kl0 + i) * 64 + bb;
                ulonglong2 h0a = *(const ulonglong2*)(h0p);
                ulonglong2 h0b = *(const ulonglong2*)(h0p + 2);
                ulonglong2 h1a = *(const ulonglong2*)(h0p + 64);
                ulonglong2 h1b = *(const ulonglong2*)(h0p + 66);
                ulonglong2 wv[6];
                wv[0] = *(const ulonglong2*)(wA + 0 * WSU + kg0 + i);
                wv[1] = *(const ulonglong2*)(wA + 1 * WSU + kg0 + i);
                wv[2] = *(const ulonglong2*)(wA + 2 * WSU + kg0 + i);
                wv[3] = *(const ulonglong2*)(wB + 0 * WSU + kg0 + i);
                wv[4] = *(const ulonglong2*)(wB + 1 * WSU + kg0 + i);
                wv[5] = *(const ulonglong2*)(wB + 2 * WSU + kg0 + i);
                ull hA[4] = {h0a.x, h0a.y, h0b.x, h0b.y};
                ull hB[4] = {h1a.x, h1a.y, h1b.x, h1b.y};
                #pragma unroll
                for (int bi = 0; bi < 4; ++bi)
                    #pragma unroll
                    for (int o = 0; o < 6; ++o) {
                        acc[bi][o] = fma2(hA[bi], wv[o].x, acc[bi][o]);
                        acc[bi][o] = fma2(hB[bi], wv[o].y, acc[bi][o]);
                    }
            }
        }

        // ---- horizontal sums: 24 floats per thread ----
        float s24[6][4];
        #pragma unroll
        for (int o = 0; o < 6; ++o)
            #pragma unroll
            for (int bi = 0; bi < 4; ++bi) {
                float2 u2 = unpk2(acc[bi][o]);
                s24[o][bi] = u2.x + u2.y;
            }

        __syncthreads();                  // all compute reads of hp done
        float4* red4 = (float4*)hpA;      // [6][512] float4 (48KB)
        #pragma unroll
        for (int o = 0; o < 6; ++o)
            red4[o * 512 + tid] = make_float4(s24[o][0], s24[o][1], s24[o][2], s24[o][3]);

        float2 ewr[4], ewz[4], ewn[4], hold[4];
        if (kh == 0) {                    // issue tail loads early (overlap with sync+LDS)
            #pragma unroll
            for (int bi = 0; bi < 4; ++bi) {
                const float* ewp = g_EW + tk[bi] * 3072;
                ewr[bi] = *(const float2*)(ewp + j0);
                ewz[bi] = *(const float2*)(ewp + 1024 + j0);
                ewn[bi] = *(const float2*)(ewp + 2048 + j0);
                hold[bi] = unpk2(hsrc[(j0 >> 1) * 64 + bb + bi]);
            }
        }
        __syncthreads();

        if (kh == 0) {
            float4 sum[6];
            #pragma unroll
            for (int o = 0; o < 6; ++o) {
                float4 sv = red4[o * 512 + tid];
                #pragma unroll
                for (int q = 1; q < 8; ++q) {
                    float4 v = red4[o * 512 + tid + (q << 6)];
                    sv.x += v.x; sv.y += v.y; sv.z += v.z; sv.w += v.w;
                }
                sum[o] = sv;
            }
            #pragma unroll
            for (int bi = 0; bi < 4; ++bi) {
                float sr0 = (&sum[0].x)[bi], sz0 = (&sum[1].x)[bi], sn0 = (&sum[2].x)[bi];
                float sr1 = (&sum[3].x)[bi], sz1 = (&sum[4].x)[bi], sn1 = (&sum[5].x)[bi];
                float r0 = 1.0f / (1.0f + expf(-(ewr[bi].x + sr0)));
                float r1 = 1.0f / (1.0f + expf(-(ewr[bi].y + sr1)));
                float z0 = 1.0f / (1.0f + expf(-(ewz[bi].x + sz0)));
                float z1 = 1.0f / (1.0f + expf(-(ewz[bi].y + sz1)));
                float n0 = tanhf(ewn[bi].x + r0 * (sn0 + bhn2.x));
                float n1 = tanhf(ewn[bi].y + r1 * (sn1 + bhn2.y));
                float h0 = (1.0f - z0) * n0 + z0 * hold[bi].x;
                float h1 = (1.0f - z1) * n1 + z1 * hold[bi].y;
                hdst[(j0 >> 1) * 64 + bb + bi] = pack2(h0, h1);
                *(float2*)(g_y + (size_t)((bb + bi) * 512 + t) * 1024 + j0) =
                    make_float2(h0, h1);
            }
            __threadfence();              // make h/y visible before release
        }

        // ---- grid barrier (fence-light, monotonic) ----
        __syncthreads();
        if (tid == 0) {
            unsigned target = (unsigned)(t + 1) * (unsigned)NCTA;
            unsigned old;
            asm volatile("atom.acq_rel.gpu.add.u32 %0, [%1], 1;"
                         : "=r"(old) : "l"(&g_cnt) : "memory");
            if (old == target - 1u) {
                asm volatile("st.release.gpu.u32 [%0], %1;"
                             :: "l"(&g_gen), "r"((unsigned)(t + 1)) : "memory");
            } else {
                unsigned v;
                do {
                    asm volatile("ld.acquire.gpu.u32 %0, [%1];"
                                 : "=r"(v) : "l"(&g_gen) : "memory");
                } while (v < (unsigned)(t + 1));
            }
        }
        __syncthreads();
    }
}

// ---------------- carry_out unpack ------------------------------------------
__global__ __launch_bounds__(256) void copy_carry(float* __restrict__ out)
{
    int idx = blockIdx.x * 256 + threadIdx.x;      // 32768 ull; final h in buffer 0
    int kp = idx >> 6, b = idx & 63;
    *(float2*)(out + b * 1024 + 2 * kp) = unpk2(g_h2[idx]);
}

// ---------------- launch ----------------------------------------------------
extern "C" void kernel_launch(void* const* d_in, const int* in_sizes, int n_in,
                              void* d_out, int out_size)
{
    const int*   toks  = (const int*)  d_in[0];
    const float* carry = (const float*)d_in[1];
    const float* emb   = (const float*)d_in[2];
    const float* Wir   = (const float*)d_in[3];
    const float* bir   = (const float*)d_in[4];
    const float* Whr   = (const float*)d_in[5];
    const float* Wiz   = (const float*)d_in[6];
    const float* biz   = (const float*)d_in[7];
    const float* Whz   = (const float*)d_in[8];
    const float* Win   = (const float*)d_in[9];
    const float* bin_  = (const float*)d_in[10];
    const float* Whn   = (const float*)d_in[11];
    const float* bhn   = (const float*)d_in[12];
    const float* Wh    = (const float*)d_in[13];
    const float* bh    = (const float*)d_in[14];
    const float* Wo    = (const float*)d_in[15];
    const float* bo    = (const float*)d_in[16];
    float* out = (float*)d_out;

    void *pY = 0, *pWc = 0, *pbc = 0;
    cudaGetSymbolAddress(&pY,  g_y);
    cudaGetSymbolAddress(&pWc, g_Wc);
    cudaGetSymbolAddress(&pbc, g_bc);

    cudaFuncSetAttribute(scan_kernel, cudaFuncAttributeMaxDynamicSharedMemorySize, SCAN_SMEM);

    prep_ew<<<128, 256>>>(emb, Wir, bir, Wiz, biz, Win, bin_);
    gemm128<<<8, 256>>>(Wh, Wo, (const float*)0, (float*)pWc);   // Wc = Wh @ Wo
    prep_misc<<<129, 256>>>(carry, bh, Wo, bo);
    scan_kernel<<<NCTA, THREADS, SCAN_SMEM>>>(toks, Whr, Whz, Whn, bhn);
    copy_carry<<<128, 256>>>(out);
    gemm128<<<256, 256>>>((const float*)pY, (const float*)pWc, (const float*)pbc,
                          out + 65536);                           // logits
}

// round 11
// speedup vs baseline: 1.8333x; 1.5446x over previous
#include <cuda_runtime.h>
#include <cuda_bf16.h>
#include <math.h>

typedef unsigned long long ull;
typedef unsigned u32;

#define NCTA 128
#define TPB 256
#define WSROW 1032                      // bf16 per weight row (pad -> conflict-free)
#define WS_BYTES (2 * 24 * WSROW * 2)   // 99072
#define ASROWB 272                      // bytes per A row (136 bf16, pad)
#define AS_PLANEB (64 * ASROWB)         // 17408
#define AS_BUFB (2 * AS_PLANEB)         // 34816
#define SMEMSZ (WS_BYTES + 2 * AS_BUFB) // 168704

__device__ float g_EW[128 * 3 * 1024];
__device__ float g_Wc[1024 * 128];
__device__ float g_bc[128];
__device__ float g_y[64u * 512u * 1024u];
__device__ __align__(16) __nv_bfloat16 g_hG[2 * 2 * 64 * 1024]; // [parity][plane][b][k]
__device__ u32 g_cnt;
__device__ u32 g_gen;

__device__ __forceinline__ u32 su32(const void* p) {
    u32 a;
    asm("{ .reg .u64 t; cvta.to.shared.u64 t, %1; cvt.u32.u64 %0, t; }" : "=r"(a) : "l"(p));
    return a;
}
__device__ __forceinline__ void cpa16(u32 d, const void* s) {
    asm volatile("cp.async.cg.shared.global [%0], [%1], 16;" :: "r"(d), "l"(s));
}
__device__ __forceinline__ void ldsm4(u32 a, u32& r0, u32& r1, u32& r2, u32& r3) {
    asm volatile("ldmatrix.sync.aligned.m8n8.x4.shared.b16 {%0,%1,%2,%3}, [%4];"
                 : "=r"(r0), "=r"(r1), "=r"(r2), "=r"(r3) : "r"(a));
}
__device__ __forceinline__ void ldsm2(u32 a, u32& r0, u32& r1) {
    asm volatile("ldmatrix.sync.aligned.m8n8.x2.shared.b16 {%0,%1}, [%2];"
                 : "=r"(r0), "=r"(r1) : "r"(a));
}
__device__ __forceinline__ void mma16816(float* d, const u32* a, const u32* b) {
    asm volatile("mma.sync.aligned.m16n8k16.row.col.f32.bf16.bf16.f32 "
        "{%0,%1,%2,%3},{%4,%5,%6,%7},{%8,%9},{%0,%1,%2,%3};"
        : "+f"(d[0]), "+f"(d[1]), "+f"(d[2]), "+f"(d[3])
        : "r"(a[0]), "r"(a[1]), "r"(a[2]), "r"(a[3]), "r"(b[0]), "r"(b[1]));
}

// ---------------- prep: EW table -------------------------------------------
__global__ __launch_bounds__(256) void prep_ew(
    const float* __restrict__ emb,
    const float* __restrict__ Wir, const float* __restrict__ bir,
    const float* __restrict__ Wiz, const float* __restrict__ biz,
    const float* __restrict__ Win, const float* __restrict__ bin_)
{
    __shared__ float se[128];
    int v = blockIdx.x, tid = threadIdx.x;
    if (tid < 128) se[tid] = emb[v * 128 + tid];
    __syncthreads();
    for (int i = tid; i < 3072; i += 256) {
        int g = i >> 10, j = i & 1023;
        const float* W  = (g == 0) ? Wir : (g == 1) ? Wiz : Win;
        const float* bb = (g == 0) ? bir : (g == 1) ? biz : bin_;
        float acc = bb[j];
        #pragma unroll 8
        for (int e = 0; e < 128; ++e) acc += se[e] * W[e * 1024 + j];
        g_EW[v * 3072 + i] = acc;
    }
}

// ---------------- prep: carry -> hG parity0, bc, counters -------------------
__global__ __launch_bounds__(256) void prep_misc(
    const float* __restrict__ carry, const float* __restrict__ bh,
    const float* __restrict__ Wo,    const float* __restrict__ bo)
{
    int bx = blockIdx.x, tid = threadIdx.x;
    if (bx < 64) {
        int b = bx;
        for (int i = 0; i < 4; ++i) {
            int k = tid + i * 256;
            float f = carry[b * 1024 + k];
            __nv_bfloat16 hi = __float2bfloat16(f);
            __nv_bfloat16 lo = __float2bfloat16(f - __bfloat162float(hi));
            g_hG[b * 1024 + k]         = hi;   // parity0 plane0
            g_hG[65536 + b * 1024 + k] = lo;   // parity0 plane1
        }
    } else {
        if (tid < 128) {
            float acc = bo[tid];
            for (int m = 0; m < 1024; ++m) acc += bh[m] * Wo[m * 128 + tid];
            g_bc[tid] = acc;
        }
        if (tid == 0) { g_cnt = 0u; g_gen = 0u; }
    }
}

// ---------------- tiled fp32 GEMM (Wc precompute + final logits) ------------
__global__ __launch_bounds__(256) void gemm128(
    const float* __restrict__ A, const float* __restrict__ Bm,
    const float* __restrict__ bias, float* __restrict__ C)
{
    __shared__ float As[32][132];
    __shared__ float Bs[32][128];
    int tid = threadIdx.x, tx = tid & 15, ty = tid >> 4, m0 = blockIdx.x * 128;
    float acc[8][8];
    #pragma unroll
    for (int i = 0; i < 8; ++i)
        #pragma unroll
        for (int j = 0; j < 8; ++j) acc[i][j] = bias ? bias[tx * 8 + j] : 0.0f;
    for (int k0 = 0; k0 < 1024; k0 += 32) {
        __syncthreads();
        #pragma unroll
        for (int i = 0; i < 4; ++i) {
            int idx = tid + i * 256, m = idx >> 3, q = idx & 7;
            float4 v = *(const float4*)(A + (size_t)(m0 + m) * 1024 + k0 + q * 4);
            As[q * 4 + 0][m] = v.x; As[q * 4 + 1][m] = v.y;
            As[q * 4 + 2][m] = v.z; As[q * 4 + 3][m] = v.w;
        }
        #pragma unroll
        for (int i = 0; i < 4; ++i) {
            int idx = tid + i * 256, r = idx >> 5, q = idx & 31;
            *(float4*)(&Bs[r][q * 4]) = *(const float4*)(Bm + (size_t)(k0 + r) * 128 + q * 4);
        }
        __syncthreads();
        #pragma unroll 4
        for (int kk = 0; kk < 32; ++kk) {
            float4 a0 = *(const float4*)(&As[kk][ty * 8]);
            float4 a1 = *(const float4*)(&As[kk][ty * 8 + 4]);
            float4 b0 = *(const float4*)(&Bs[kk][tx * 8]);
            float4 b1 = *(const float4*)(&Bs[kk][tx * 8 + 4]);
            float av[8] = {a0.x, a0.y, a0.z, a0.w, a1.x, a1.y, a1.z, a1.w};
            float bv[8] = {b0.x, b0.y, b0.z, b0.w, b1.x, b1.y, b1.z, b1.w};
            #pragma unroll
            for (int i = 0; i < 8; ++i)
                #pragma unroll
                for (int j = 0; j < 8; ++j) acc[i][j] = fmaf(av[i], bv[j], acc[i][j]);
        }
    }
    #pragma unroll
    for (int i = 0; i < 8; ++i) {
        float* cp = C + (size_t)(m0 + ty * 8 + i) * 128 + tx * 8;
        *(float4*)cp       = make_float4(acc[i][0], acc[i][1], acc[i][2], acc[i][3]);
        *(float4*)(cp + 4) = make_float4(acc[i][4], acc[i][5], acc[i][6], acc[i][7]);
    }
}

// ---------------- staging: h chunk (k128) into As buf -----------------------
__device__ __forceinline__ void stageA(u32 as_base, int buf, int chunk, int p, int tid)
{
    const __nv_bfloat16* src0 = g_hG + (size_t)p * 131072;
    #pragma unroll
    for (int i2 = 0; i2 < 8; ++i2) {
        int u = tid + i2 * 256;                    // 0..2047
        int plane = u >> 10, rem = u & 1023, b = rem >> 4, kc = rem & 15;
        const __nv_bfloat16* src = src0 + plane * 65536 + b * 1024 + chunk * 128 + kc * 8;
        u32 dst = as_base + buf * AS_BUFB + plane * AS_PLANEB + b * ASROWB + kc * 16;
        cpa16(dst, src);
    }
    asm volatile("cp.async.commit_group;" ::: "memory");
}

// ---------------- persistent mma.sync GRU scan ------------------------------
__global__ void __launch_bounds__(TPB, 1) scan_kernel(
    const int* __restrict__ toks,
    const float* __restrict__ Whr, const float* __restrict__ Whz,
    const float* __restrict__ Whn, const float* __restrict__ bhn,
    const float* __restrict__ carry, float* __restrict__ outc)
{
    extern __shared__ char sm[];
    __nv_bfloat16* Ws = (__nv_bfloat16*)sm;
    const u32 smb = su32(sm);
    const u32 as_base = smb + WS_BYTES;
    float* red = (float*)(sm + WS_BYTES);          // reuse As area between steps

    const int tid = threadIdx.x, bx = blockIdx.x;
    const int lane = tid & 31, w = tid >> 5;
    const int kq = w >> 1, mpair = w & 1;
    const int j0 = bx * 8;
    const int c0 = (lane & 3) * 2;                 // this thread's jl pair

    // ---- weights -> smem bf16 hi/lo, once ----
    for (int idx = tid; idx < 24 * 1024; idx += TPB) {
        int c = idx >> 10, k = idx & 1023;
        int g = c >> 3, jl = c & 7;
        const float* Wg = (g == 0) ? Whr : (g == 1) ? Whz : Whn;
        float wv = Wg[(size_t)k * 1024 + j0 + jl];
        __nv_bfloat16 hi = __float2bfloat16(wv);
        Ws[c * WSROW + k] = hi;
        Ws[24 * WSROW + c * WSROW + k] = __float2bfloat16(wv - __bfloat162float(hi));
    }

    // ---- persistent per-thread state (finisher warps kq==0) ----
    float hreg[8], bhn2[2];
    if (kq == 0) {
        bhn2[0] = bhn[j0 + c0]; bhn2[1] = bhn[j0 + c0 + 1];
        #pragma unroll
        for (int mt = 0; mt < 2; ++mt)
            #pragma unroll
            for (int h2 = 0; h2 < 2; ++h2) {
                int b = 32 * mpair + 16 * mt + (lane >> 2) + 8 * h2;
                hreg[mt * 4 + h2 * 2 + 0] = carry[b * 1024 + j0 + c0];
                hreg[mt * 4 + h2 * 2 + 1] = carry[b * 1024 + j0 + c0 + 1];
            }
    }
    __syncthreads();

    // precomputed ldmatrix lane addresses (k-variable added per use)
    const u32 aAddr0 = as_base + (32 * mpair + (lane & 15)) * ASROWB + (lane >> 4) * 16;
    const u32 bAddr0 = smb + ((lane & 7) * WSROW) * 2 + ((lane >> 3) & 1) * 16;

    for (int t = 0; t < 512; ++t) {
        const int p = t & 1;
        stageA(as_base, 0, 0, p, tid);

        float acc[2][3][4];
        float* accf = &acc[0][0][0];
        #pragma unroll
        for (int i = 0; i < 24; ++i) accf[i] = 0.0f;

        #pragma unroll 1
        for (int c = 0; c < 8; ++c) {
            asm volatile("cp.async.wait_group 0;" ::: "memory");
            __syncthreads();
            if (c < 7) stageA(as_base, (c + 1) & 1, c + 1, p, tid);
            const u32 abuf = aAddr0 + (u32)((c & 1) * AS_BUFB);
            const u32 bk = (u32)(c * 256);
            #pragma unroll
            for (int s2 = 0; s2 < 2; ++s2) {
                const int ks = kq + s2 * 4;
                u32 aH[2][4], aL[2][4], bH[3][2], bL[3][2];
                #pragma unroll
                for (int mt = 0; mt < 2; ++mt) {
                    u32 a = abuf + mt * (16 * ASROWB) + ks * 32;
                    ldsm4(a, aH[mt][0], aH[mt][1], aH[mt][2], aH[mt][3]);
                    ldsm4(a + AS_PLANEB, aL[mt][0], aL[mt][1], aL[mt][2], aL[mt][3]);
                }
                #pragma unroll
                for (int nt = 0; nt < 3; ++nt) {
                    u32 b = bAddr0 + nt * (8 * WSROW * 2) + bk + ks * 32;
                    ldsm2(b, bH[nt][0], bH[nt][1]);
                    ldsm2(b + 24 * WSROW * 2, bL[nt][0], bL[nt][1]);
                }
                #pragma unroll
                for (int mt = 0; mt < 2; ++mt)
                    #pragma unroll
                    for (int nt = 0; nt < 3; ++nt) {
                        mma16816(acc[mt][nt], aH[mt], bH[nt]);
                        mma16816(acc[mt][nt], aH[mt], bL[nt]);
                        mma16816(acc[mt][nt], aL[mt], bH[nt]);
                    }
            }
            __syncthreads();
        }

        // ---- cross-kq reduction ----
        if (kq > 0) {
            float* rp = red + (size_t)((kq - 1) * 64 + mpair * 32 + lane) * 24;
            #pragma unroll
            for (int i = 0; i < 24; ++i) rp[i] = accf[i];
        }
        __syncthreads();

        if (kq == 0) {
            #pragma unroll
            for (int q = 0; q < 3; ++q) {
                const float* rp = red + (size_t)(q * 64 + mpair * 32 + lane) * 24;
                #pragma unroll
                for (int i = 0; i < 24; ++i) accf[i] += rp[i];
            }
            // ---- GRU update (thread-local) ----
            #pragma unroll
            for (int mt = 0; mt < 2; ++mt)
                #pragma unroll
                for (int h2 = 0; h2 < 2; ++h2) {
                    int b = 32 * mpair + 16 * mt + (lane >> 2) + 8 * h2;
                    int tok = toks[b * 512 + t];
                    const float* ewp = g_EW + (size_t)tok * 3072 + j0 + c0;
                    float2 er = *(const float2*)ewp;
                    float2 ez = *(const float2*)(ewp + 1024);
                    float2 en = *(const float2*)(ewp + 2048);
                    float hn[2];
                    #pragma unroll
                    for (int i = 0; i < 2; ++i) {
                        float pr = acc[mt][0][2 * h2 + i];
                        float pz = acc[mt][1][2 * h2 + i];
                        float pn = acc[mt][2][2 * h2 + i];
                        float rr = 1.0f / (1.0f + expf(-((i ? er.y : er.x) + pr)));
                        float zz = 1.0f / (1.0f + expf(-((i ? ez.y : ez.x) + pz)));
                        float nn = tanhf((i ? en.y : en.x) + rr * (pn + bhn2[i]));
                        float ho = hreg[mt * 4 + h2 * 2 + i];
                        hn[i] = (1.0f - zz) * nn + zz * ho;
                        hreg[mt * 4 + h2 * 2 + i] = hn[i];
                    }
                    *(float2*)(g_y + (size_t)(b * 512 + t) * 1024 + j0 + c0) =
                        make_float2(hn[0], hn[1]);
                    __nv_bfloat16 h0 = __float2bfloat16(hn[0]);
                    __nv_bfloat16 h1 = __float2bfloat16(hn[1]);
                    __nv_bfloat16 l0 = __float2bfloat16(hn[0] - __bfloat162float(h0));
                    __nv_bfloat16 l1 = __float2bfloat16(hn[1] - __bfloat162float(h1));
                    int pd = (p ^ 1) * 131072 + b * 1024 + j0 + c0;
                    *(u32*)(g_hG + pd) =
                        (u32)__bfloat16_as_ushort(h0) | ((u32)__bfloat16_as_ushort(h1) << 16);
                    *(u32*)(g_hG + pd + 65536) =
                        (u32)__bfloat16_as_ushort(l0) | ((u32)__bfloat16_as_ushort(l1) << 16);
                    if (t == 511)
                        *(float2*)(outc + b * 1024 + j0 + c0) = make_float2(hn[0], hn[1]);
                }
            __threadfence();
        }

        // ---- grid barrier (fence-light, monotonic) ----
        __syncthreads();
        if (tid == 0) {
            u32 target = (u32)(t + 1) * (u32)NCTA, old;
            asm volatile("atom.acq_rel.gpu.add.u32 %0, [%1], 1;"
                         : "=r"(old) : "l"(&g_cnt) : "memory");
            if (old == target - 1u) {
                asm volatile("st.release.gpu.u32 [%0], %1;"
                             :: "l"(&g_gen), "r"((u32)(t + 1)) : "memory");
            } else {
                u32 v;
                do {
                    asm volatile("ld.acquire.gpu.u32 %0, [%1];" : "=r"(v) : "l"(&g_gen) : "memory");
                } while (v < (u32)(t + 1));
            }
        }
        __syncthreads();
    }
}

// ---------------- launch ----------------------------------------------------
extern "C" void kernel_launch(void* const* d_in, const int* in_sizes, int n_in,
                              void* d_out, int out_size)
{
    const int*   toks  = (const int*)  d_in[0];
    const float* carry = (const float*)d_in[1];
    const float* emb   = (const float*)d_in[2];
    const float* Wir   = (const float*)d_in[3];
    const float* bir   = (const float*)d_in[4];
    const float* Whr   = (const float*)d_in[5];
    const float* Wiz   = (const float*)d_in[6];
    const float* biz   = (const float*)d_in[7];
    const float* Whz   = (const float*)d_in[8];
    const float* Win   = (const float*)d_in[9];
    const float* bin_  = (const float*)d_in[10];
    const float* Whn   = (const float*)d_in[11];
    const float* bhn   = (const float*)d_in[12];
    const float* Wh    = (const float*)d_in[13];
    const float* bh    = (const float*)d_in[14];
    const float* Wo    = (const float*)d_in[15];
    const float* bo    = (const float*)d_in[16];
    float* out = (float*)d_out;

    void *pY = 0, *pWc = 0, *pbc = 0;
    cudaGetSymbolAddress(&pY, g_y);
    cudaGetSymbolAddress(&pWc, g_Wc);
    cudaGetSymbolAddress(&pbc, g_bc);
    cudaFuncSetAttribute(scan_kernel, cudaFuncAttributeMaxDynamicSharedMemorySize, SMEMSZ);

    prep_ew<<<128, 256>>>(emb, Wir, bir, Wiz, biz, Win, bin_);
    gemm128<<<8, 256>>>(Wh, Wo, (const float*)0, (float*)pWc);
    prep_misc<<<65, 256>>>(carry, bh, Wo, bo);
    scan_kernel<<<NCTA, TPB, SMEMSZ>>>(toks, Whr, Whz, Whn, bhn, carry, out);
    gemm128<<<256, 256>>>((const float*)pY, (const float*)pWc, (const float*)pbc,
                          out + 65536);
}

// round 12
// speedup vs baseline: 2.2800x; 1.2436x over previous
#include <cuda_runtime.h>
#include <cuda_bf16.h>
#include <math.h>

typedef unsigned long long ull;
typedef unsigned u32;

#define NCTA 128
#define TPB 256
#define WSROW 1032                      // bf16 per weight row (pad -> conflict-free)
#define WS_BYTES (2 * 24 * WSROW * 2)   // 99072
#define ASROWB 272                      // bytes per A row (136 bf16, pad)
#define AS_PLANEB (64 * ASROWB)         // 17408
#define AS_BUFB (2 * AS_PLANEB)         // 34816
#define SMEMSZ (WS_BYTES + 3 * AS_BUFB) // 203520

__device__ float g_EW[128 * 3 * 1024];
__device__ float g_Wc[1024 * 128];
__device__ float g_bc[128];
__device__ float g_y[64u * 512u * 1024u];
__device__ __align__(16) __nv_bfloat16 g_hG[2 * 2 * 64 * 1024]; // [parity][plane][b][k]
__device__ u32 g_cnt;
__device__ u32 g_gen;

__device__ __forceinline__ u32 su32(const void* p) {
    u32 a;
    asm("{ .reg .u64 t; cvta.to.shared.u64 t, %1; cvt.u32.u64 %0, t; }" : "=r"(a) : "l"(p));
    return a;
}
__device__ __forceinline__ void cpa16(u32 d, const void* s) {
    asm volatile("cp.async.cg.shared.global [%0], [%1], 16;" :: "r"(d), "l"(s));
}
__device__ __forceinline__ void ldsm4(u32 a, u32& r0, u32& r1, u32& r2, u32& r3) {
    asm volatile("ldmatrix.sync.aligned.m8n8.x4.shared.b16 {%0,%1,%2,%3}, [%4];"
                 : "=r"(r0), "=r"(r1), "=r"(r2), "=r"(r3) : "r"(a));
}
__device__ __forceinline__ void ldsm2(u32 a, u32& r0, u32& r1) {
    asm volatile("ldmatrix.sync.aligned.m8n8.x2.shared.b16 {%0,%1}, [%2];"
                 : "=r"(r0), "=r"(r1) : "r"(a));
}
__device__ __forceinline__ void mma16816(float* d, const u32* a, const u32* b) {
    asm volatile("mma.sync.aligned.m16n8k16.row.col.f32.bf16.bf16.f32 "
        "{%0,%1,%2,%3},{%4,%5,%6,%7},{%8,%9},{%0,%1,%2,%3};"
        : "+f"(d[0]), "+f"(d[1]), "+f"(d[2]), "+f"(d[3])
        : "r"(a[0]), "r"(a[1]), "r"(a[2]), "r"(a[3]), "r"(b[0]), "r"(b[1]));
}
__device__ __forceinline__ float fsig(float x) {
    return __fdividef(1.0f, 1.0f + __expf(-x));
}
__device__ __forceinline__ float ftanh(float x) {
    float e = __expf(-2.0f * fabsf(x));
    float t = __fdividef(1.0f - e, 1.0f + e);
    return copysignf(t, x);
}

// ---------------- prep: EW table -------------------------------------------
__global__ __launch_bounds__(256) void prep_ew(
    const float* __restrict__ emb,
    const float* __restrict__ Wir, const float* __restrict__ bir,
    const float* __restrict__ Wiz, const float* __restrict__ biz,
    const float* __restrict__ Win, const float* __restrict__ bin_)
{
    __shared__ float se[128];
    int v = blockIdx.x, tid = threadIdx.x;
    if (tid < 128) se[tid] = emb[v * 128 + tid];
    __syncthreads();
    for (int i = tid; i < 3072; i += 256) {
        int g = i >> 10, j = i & 1023;
        const float* W  = (g == 0) ? Wir : (g == 1) ? Wiz : Win;
        const float* bb = (g == 0) ? bir : (g == 1) ? biz : bin_;
        float acc = bb[j];
        #pragma unroll 8
        for (int e = 0; e < 128; ++e) acc += se[e] * W[e * 1024 + j];
        g_EW[v * 3072 + i] = acc;
    }
}

// ---------------- prep: carry -> hG parity0, bc, counters -------------------
__global__ __launch_bounds__(256) void prep_misc(
    const float* __restrict__ carry, const float* __restrict__ bh,
    const float* __restrict__ Wo,    const float* __restrict__ bo)
{
    int bx = blockIdx.x, tid = threadIdx.x;
    if (bx < 64) {
        int b = bx;
        for (int i = 0; i < 4; ++i) {
            int k = tid + i * 256;
            float f = carry[b * 1024 + k];
            __nv_bfloat16 hi = __float2bfloat16(f);
            __nv_bfloat16 lo = __float2bfloat16(f - __bfloat162float(hi));
            g_hG[b * 1024 + k]         = hi;
            g_hG[65536 + b * 1024 + k] = lo;
        }
    } else {
        if (tid < 128) {
            float acc = bo[tid];
            for (int m = 0; m < 1024; ++m) acc += bh[m] * Wo[m * 128 + tid];
            g_bc[tid] = acc;
        }
        if (tid == 0) { g_cnt = 0u; g_gen = 0u; }
    }
}

// ---------------- tiled fp32 GEMM (Wc precompute + final logits) ------------
__global__ __launch_bounds__(256) void gemm128(
    const float* __restrict__ A, const float* __restrict__ Bm,
    const float* __restrict__ bias, float* __restrict__ C)
{
    __shared__ float As[32][132];
    __shared__ float Bs[32][128];
    int tid = threadIdx.x, tx = tid & 15, ty = tid >> 4, m0 = blockIdx.x * 128;
    float acc[8][8];
    #pragma unroll
    for (int i = 0; i < 8; ++i)
        #pragma unroll
        for (int j = 0; j < 8; ++j) acc[i][j] = bias ? bias[tx * 8 + j] : 0.0f;
    for (int k0 = 0; k0 < 1024; k0 += 32) {
        __syncthreads();
        #pragma unroll
        for (int i = 0; i < 4; ++i) {
            int idx = tid + i * 256, m = idx >> 3, q = idx & 7;
            float4 v = *(const float4*)(A + (size_t)(m0 + m) * 1024 + k0 + q * 4);
            As[q * 4 + 0][m] = v.x; As[q * 4 + 1][m] = v.y;
            As[q * 4 + 2][m] = v.z; As[q * 4 + 3][m] = v.w;
        }
        #pragma unroll
        for (int i = 0; i < 4; ++i) {
            int idx = tid + i * 256, r = idx >> 5, q = idx & 31;
            *(float4*)(&Bs[r][q * 4]) = *(const float4*)(Bm + (size_t)(k0 + r) * 128 + q * 4);
        }
        __syncthreads();
        #pragma unroll 4
        for (int kk = 0; kk < 32; ++kk) {
            float4 a0 = *(const float4*)(&As[kk][ty * 8]);
            float4 a1 = *(const float4*)(&As[kk][ty * 8 + 4]);
            float4 b0 = *(const float4*)(&Bs[kk][tx * 8]);
            float4 b1 = *(const float4*)(&Bs[kk][tx * 8 + 4]);
            float av[8] = {a0.x, a0.y, a0.z, a0.w, a1.x, a1.y, a1.z, a1.w};
            float bv[8] = {b0.x, b0.y, b0.z, b0.w, b1.x, b1.y, b1.z, b1.w};
            #pragma unroll
            for (int i = 0; i < 8; ++i)
                #pragma unroll
                for (int j = 0; j < 8; ++j) acc[i][j] = fmaf(av[i], bv[j], acc[i][j]);
        }
    }
    #pragma unroll
    for (int i = 0; i < 8; ++i) {
        float* cp = C + (size_t)(m0 + ty * 8 + i) * 128 + tx * 8;
        *(float4*)cp       = make_float4(acc[i][0], acc[i][1], acc[i][2], acc[i][3]);
        *(float4*)(cp + 4) = make_float4(acc[i][4], acc[i][5], acc[i][6], acc[i][7]);
    }
}

// ---------------- staging: h chunk (k128) into As buf 0..2 ------------------
__device__ __forceinline__ void stageA(u32 as_base, int buf, int chunk, int p, int tid)
{
    const __nv_bfloat16* src0 = g_hG + (size_t)p * 131072;
    #pragma unroll
    for (int i2 = 0; i2 < 8; ++i2) {
        int u = tid + i2 * 256;                    // 0..2047
        int plane = u >> 10, rem = u & 1023, b = rem >> 4, kc = rem & 15;
        const __nv_bfloat16* src = src0 + plane * 65536 + b * 1024 + chunk * 128 + kc * 8;
        u32 dst = as_base + buf * AS_BUFB + plane * AS_PLANEB + b * ASROWB + kc * 16;
        cpa16(dst, src);
    }
    asm volatile("cp.async.commit_group;" ::: "memory");
}

// ---------------- persistent mma.sync GRU scan ------------------------------
__global__ void __launch_bounds__(TPB, 1) scan_kernel(
    const int* __restrict__ toks,
    const float* __restrict__ Whr, const float* __restrict__ Whz,
    const float* __restrict__ Whn, const float* __restrict__ bhn,
    const float* __restrict__ carry, float* __restrict__ outc)
{
    extern __shared__ char sm[];
    __nv_bfloat16* Ws = (__nv_bfloat16*)sm;
    const u32 smb = su32(sm);
    const u32 as_base = smb + WS_BYTES;
    float* red = (float*)(sm + WS_BYTES + 2 * AS_BUFB);  // buf2 region (safe post iter-6 sync)

    const int tid = threadIdx.x, bx = blockIdx.x;
    const int lane = tid & 31, w = tid >> 5;
    const int kq = w >> 1, mpair = w & 1;
    const int j0 = bx * 8;
    const int c0 = (lane & 3) * 2;

    // ---- weights -> smem bf16 hi/lo, once ----
    for (int idx = tid; idx < 24 * 1024; idx += TPB) {
        int c = idx >> 10, k = idx & 1023;
        int g = c >> 3, jl = c & 7;
        const float* Wg = (g == 0) ? Whr : (g == 1) ? Whz : Whn;
        float wv = Wg[(size_t)k * 1024 + j0 + jl];
        __nv_bfloat16 hi = __float2bfloat16(wv);
        Ws[c * WSROW + k] = hi;
        Ws[24 * WSROW + c * WSROW + k] = __float2bfloat16(wv - __bfloat162float(hi));
    }

    // ---- per-thread persistent state: combo (mt,h2) = (kq&1, kq>>1) ----
    const int mt_o = kq & 1, h2_o = kq >> 1;
    const int b_o = 32 * mpair + 16 * mt_o + (lane >> 2) + 8 * h2_o;
    float hreg[2], bhn2[2];
    bhn2[0] = bhn[j0 + c0]; bhn2[1] = bhn[j0 + c0 + 1];
    hreg[0] = carry[b_o * 1024 + j0 + c0];
    hreg[1] = carry[b_o * 1024 + j0 + c0 + 1];
    __syncthreads();

    const u32 aAddr0 = as_base + (32 * mpair + (lane & 15)) * ASROWB + (lane >> 4) * 16;
    const u32 bAddr0 = smb + ((lane & 7) * WSROW) * 2 + ((lane >> 3) & 1) * 16;

    for (int t = 0; t < 512; ++t) {
        const int p = t & 1;
        stageA(as_base, 0, 0, p, tid);
        stageA(as_base, 1, 1, p, tid);

        float acc[2][3][4];
        float* accf = &acc[0][0][0];
        #pragma unroll
        for (int i = 0; i < 24; ++i) accf[i] = 0.0f;

        #pragma unroll 1
        for (int c = 0; c < 8; ++c) {
            if (c < 7) asm volatile("cp.async.wait_group 1;" ::: "memory");
            else       asm volatile("cp.async.wait_group 0;" ::: "memory");
            __syncthreads();
            if (c < 6) stageA(as_base, (c + 2) % 3, c + 2, p, tid);
            const u32 abuf = aAddr0 + (u32)((c % 3) * AS_BUFB);
            const u32 bk = (u32)(c * 256);
            #pragma unroll
            for (int s2 = 0; s2 < 2; ++s2) {
                const int ks = kq + s2 * 4;
                u32 aH[2][4], aL[2][4], bH[3][2], bL[3][2];
                #pragma unroll
                for (int mt = 0; mt < 2; ++mt) {
                    u32 a = abuf + mt * (16 * ASROWB) + ks * 32;
                    ldsm4(a, aH[mt][0], aH[mt][1], aH[mt][2], aH[mt][3]);
                    ldsm4(a + AS_PLANEB, aL[mt][0], aL[mt][1], aL[mt][2], aL[mt][3]);
                }
                #pragma unroll
                for (int nt = 0; nt < 3; ++nt) {
                    u32 b = bAddr0 + nt * (8 * WSROW * 2) + bk + ks * 32;
                    ldsm2(b, bH[nt][0], bH[nt][1]);
                    ldsm2(b + 24 * WSROW * 2, bL[nt][0], bL[nt][1]);
                }
                #pragma unroll
                for (int mt = 0; mt < 2; ++mt)
                    #pragma unroll
                    for (int nt = 0; nt < 3; ++nt) {
                        mma16816(acc[mt][nt], aH[mt], bH[nt]);
                        mma16816(acc[mt][nt], aH[mt], bL[nt]);
                        mma16816(acc[mt][nt], aL[mt], bH[nt]);
                    }
            }
        }

        // ---- all threads publish partials (rows padded to 25: conflict-free)
        {
            float* rp = red + tid * 25;
            #pragma unroll
            for (int i = 0; i < 24; ++i) rp[i] = accf[i];
        }
        __syncthreads();

        // ---- each thread: gather 4 partials for its combo, GRU update ----
        {
            float s6[6];
            #pragma unroll
            for (int nt = 0; nt < 3; ++nt)
                #pragma unroll
                for (int i = 0; i < 2; ++i) {
                    int idx = mt_o * 12 + nt * 4 + 2 * h2_o + i;
                    float v = 0.0f;
                    #pragma unroll
                    for (int q2 = 0; q2 < 4; ++q2)
                        v += red[(q2 * 64 + mpair * 32 + lane) * 25 + idx];
                    s6[nt * 2 + i] = v;
                }
            int tok = toks[b_o * 512 + t];
            const float* ewp = g_EW + (size_t)tok * 3072 + j0 + c0;
            float2 er = *(const float2*)ewp;
            float2 ez = *(const float2*)(ewp + 1024);
            float2 en = *(const float2*)(ewp + 2048);
            float hn[2];
            #pragma unroll
            for (int i = 0; i < 2; ++i) {
                float rr = fsig((i ? er.y : er.x) + s6[0 + i]);
                float zz = fsig((i ? ez.y : ez.x) + s6[2 + i]);
                float nn = ftanh((i ? en.y : en.x) + rr * (s6[4 + i] + bhn2[i]));
                hn[i] = (1.0f - zz) * nn + zz * hreg[i];
                hreg[i] = hn[i];
            }
            *(float2*)(g_y + (size_t)(b_o * 512 + t) * 1024 + j0 + c0) =
                make_float2(hn[0], hn[1]);
            __nv_bfloat16 h0 = __float2bfloat16(hn[0]);
            __nv_bfloat16 h1 = __float2bfloat16(hn[1]);
            __nv_bfloat16 l0 = __float2bfloat16(hn[0] - __bfloat162float(h0));
            __nv_bfloat16 l1 = __float2bfloat16(hn[1] - __bfloat162float(h1));
            int pd = (p ^ 1) * 131072 + b_o * 1024 + j0 + c0;
            *(u32*)(g_hG + pd) =
                (u32)__bfloat16_as_ushort(h0) | ((u32)__bfloat16_as_ushort(h1) << 16);
            *(u32*)(g_hG + pd + 65536) =
                (u32)__bfloat16_as_ushort(l0) | ((u32)__bfloat16_as_ushort(l1) << 16);
            if (t == 511)
                *(float2*)(outc + b_o * 1024 + j0 + c0) = make_float2(hn[0], hn[1]);
            __threadfence();
        }

        // ---- grid barrier (fence-light, monotonic) ----
        __syncthreads();
        if (tid == 0) {
            u32 target = (u32)(t + 1) * (u32)NCTA, old;
            asm volatile("atom.acq_rel.gpu.add.u32 %0, [%1], 1;"
                         : "=r"(old) : "l"(&g_cnt) : "memory");
            if (old == target - 1u) {
                asm volatile("st.release.gpu.u32 [%0], %1;"
                             :: "l"(&g_gen), "r"((u32)(t + 1)) : "memory");
            } else {
                u32 v;
                do {
                    asm volatile("ld.acquire.gpu.u32 %0, [%1];" : "=r"(v) : "l"(&g_gen) : "memory");
                } while (v < (u32)(t + 1));
            }
        }
        __syncthreads();
    }
}

// ---------------- launch ----------------------------------------------------
extern "C" void kernel_launch(void* const* d_in, const int* in_sizes, int n_in,
                              void* d_out, int out_size)
{
    const int*   toks  = (const int*)  d_in[0];
    const float* carry = (const float*)d_in[1];
    const float* emb   = (const float*)d_in[2];
    const float* Wir   = (const float*)d_in[3];
    const float* bir   = (const float*)d_in[4];
    const float* Whr   = (const float*)d_in[5];
    const float* Wiz   = (const float*)d_in[6];
    const float* biz   = (const float*)d_in[7];
    const float* Whz   = (const float*)d_in[8];
    const float* Win   = (const float*)d_in[9];
    const float* bin_  = (const float*)d_in[10];
    const float* Whn   = (const float*)d_in[11];
    const float* bhn   = (const float*)d_in[12];
    const float* Wh    = (const float*)d_in[13];
    const float* bh    = (const float*)d_in[14];
    const float* Wo    = (const float*)d_in[15];
    const float* bo    = (const float*)d_in[16];
    float* out = (float*)d_out;

    void *pY = 0, *pWc = 0, *pbc = 0;
    cudaGetSymbolAddress(&pY, g_y);
    cudaGetSymbolAddress(&pWc, g_Wc);
    cudaGetSymbolAddress(&pbc, g_bc);
    cudaFuncSetAttribute(scan_kernel, cudaFuncAttributeMaxDynamicSharedMemorySize, SMEMSZ);

    prep_ew<<<128, 256>>>(emb, Wir, bir, Wiz, biz, Win, bin_);
    gemm128<<<8, 256>>>(Wh, Wo, (const float*)0, (float*)pWc);
    prep_misc<<<65, 256>>>(carry, bh, Wo, bo);
    scan_kernel<<<NCTA, TPB, SMEMSZ>>>(toks, Whr, Whz, Whn, bhn, carry, out);
    gemm128<<<256, 256>>>((const float*)pY, (const float*)pWc, (const float*)pbc,
                          out + 65536);
}